// round 17
// baseline (speedup 1.0000x reference)
#include <cuda_runtime.h>
#include <cuda_bf16.h>
#include <cuda_fp16.h>
#include <cstdint>

#define NN 50000
#define FIN 128
#define FOUT 40
#define EMAX 1600000
#define BN_EPS 1e-5f

// ---------------- device scratch ----------------
__device__ int2     d_t0h[NN * 32];           // fp16 gemm output (128 halfs = 32 int2 per row)
__device__ int2     d_t1h[NN * 32];           // fp16 spmm output (activations)
__device__ __half   d_t2h[NN * FOUT + 64];    // fp16 layer-2 gemm output
__device__ int2     d_ecolw[EMAX];
__device__ int      d_epos[EMAX];
__device__ int      d_counts[NN];
__device__ int      d_rowptr[NN + 1];
__device__ float    d_sum[2][FIN];
__device__ float    d_sumsq[2][FIN];
__device__ uint32_t d_Whi[2 * 4 * 128 * 16];  // pre-split W (hi), [layer][kt][n][k2]
__device__ uint32_t d_Wlo[2 * 4 * 128 * 16];  // pre-split W (lo)

// ---------------- fp16-split helpers ----------------
__device__ __forceinline__ void h16_split(float a, __half& hi, __half& lo) {
    hi = __float2half_rn(a);
    lo = __float2half_rn(a - __half2float(hi));
}

__device__ __forceinline__ uint32_t pack_h2(__half a, __half b) {
    __half2 h = __halves2half2(a, b);
    return *reinterpret_cast<uint32_t*>(&h);
}

__device__ __forceinline__ void mma_f16(float* c, const uint32_t* a, uint32_t b0, uint32_t b1) {
    asm volatile("mma.sync.aligned.m16n8k16.row.col.f32.f16.f16.f32 "
        "{%0,%1,%2,%3}, {%4,%5,%6,%7}, {%8,%9}, {%0,%1,%2,%3};"
        : "+f"(c[0]), "+f"(c[1]), "+f"(c[2]), "+f"(c[3])
        : "r"(a[0]), "r"(a[1]), "r"(a[2]), "r"(a[3]), "r"(b0), "r"(b1));
}

// ---------------- zero + W pre-split ----------------
// W split layout: index ((layer*4+kt)*128+n)*16+k2; per-layer region = 8192 = 2^13 entries.
__global__ void zero_kernel(const float* __restrict__ W0, const float* __restrict__ W1) {
    int i = blockIdx.x * blockDim.x + threadIdx.x;
    if (i < NN) d_counts[i] = 0;
    if (i < FIN) {
        d_sum[0][i] = 0.f; d_sum[1][i] = 0.f;
        d_sumsq[0][i] = 0.f; d_sumsq[1][i] = 0.f;
    }
    if (i < 2 * 4 * 128 * 16) {
        int layer = i >> 13;
        int r = i & 8191;
        int kt = r >> 11;
        int e = r & 2047;
        int n = e >> 4;
        int k2 = e & 15;
        const float* W = layer ? W1 : W0;
        float w0 = W[(kt * 32 + 2 * k2) * 128 + n];
        float w1 = W[(kt * 32 + 2 * k2 + 1) * 128 + n];
        __half h0, l0, h1, l1;
        h16_split(w0, h0, l0);
        h16_split(w1, h1, l1);
        d_Whi[i] = pack_h2(h0, h1);
        d_Wlo[i] = pack_h2(l0, l1);
    }
}

// ---------------- CSR build pieces (16 edges/thread, front-batched) ----------------
__device__ __forceinline__ void hist_body(const int* __restrict__ er, int E, int bid) {
    int i = bid * 256 + threadIdx.x;
    int e0 = i * 16;
    if (e0 + 16 <= E) {
        int4 r[4];
#pragma unroll
        for (int q = 0; q < 4; ++q)
            r[q] = *reinterpret_cast<const int4*>(&er[e0 + 4 * q]);
#pragma unroll
        for (int q = 0; q < 4; ++q) {
            int4 p;
            p.x = atomicAdd(&d_counts[r[q].x], 1);
            p.y = atomicAdd(&d_counts[r[q].y], 1);
            p.z = atomicAdd(&d_counts[r[q].z], 1);
            p.w = atomicAdd(&d_counts[r[q].w], 1);
            *reinterpret_cast<int4*>(&d_epos[e0 + 4 * q]) = p;
        }
    } else {
        for (int e = e0; e < E; ++e) d_epos[e] = atomicAdd(&d_counts[er[e]], 1);
    }
}

__device__ __forceinline__ void scatter_body(const int* __restrict__ er, const int* __restrict__ ec,
                                             const float* __restrict__ ew, int E, int bid) {
    int i = bid * 256 + threadIdx.x;
    int e0 = i * 16;
    if (e0 + 16 <= E) {
        int4 r[4], c[4], p[4];
        float4 w[4];
#pragma unroll
        for (int q = 0; q < 4; ++q) {
            r[q] = *reinterpret_cast<const int4*>(&er[e0 + 4 * q]);
            c[q] = *reinterpret_cast<const int4*>(&ec[e0 + 4 * q]);
            w[q] = *reinterpret_cast<const float4*>(&ew[e0 + 4 * q]);
            p[q] = *reinterpret_cast<const int4*>(&d_epos[e0 + 4 * q]);
        }
        int b[16];
#pragma unroll
        for (int q = 0; q < 4; ++q) {
            b[4 * q + 0] = d_rowptr[r[q].x];
            b[4 * q + 1] = d_rowptr[r[q].y];
            b[4 * q + 2] = d_rowptr[r[q].z];
            b[4 * q + 3] = d_rowptr[r[q].w];
        }
#pragma unroll
        for (int q = 0; q < 4; ++q) {
            d_ecolw[b[4 * q + 0] + p[q].x] = make_int2(c[q].x, __float_as_int(w[q].x));
            d_ecolw[b[4 * q + 1] + p[q].y] = make_int2(c[q].y, __float_as_int(w[q].y));
            d_ecolw[b[4 * q + 2] + p[q].z] = make_int2(c[q].z, __float_as_int(w[q].z));
            d_ecolw[b[4 * q + 3] + p[q].w] = make_int2(c[q].w, __float_as_int(w[q].w));
        }
    } else {
        for (int e = e0; e < E; ++e) {
            int pos = d_rowptr[er[e]] + d_epos[e];
            d_ecolw[pos] = make_int2(ec[e], __float_as_int(ew[e]));
        }
    }
}

__global__ void scan_kernel(int Nn) {
    __shared__ int ssum[1024];
    int t = threadIdx.x;
    int chunk = (Nn + 1023) >> 10;
    int base = t * chunk;
    int s = 0;
    for (int i = 0; i < chunk; ++i) {
        int idx = base + i;
        if (idx < Nn) s += d_counts[idx];
    }
    ssum[t] = s;
    __syncthreads();
    for (int off = 1; off < 1024; off <<= 1) {
        int v = (t >= off) ? ssum[t - off] : 0;
        __syncthreads();
        ssum[t] += v;
        __syncthreads();
    }
    int run = (t > 0) ? ssum[t - 1] : 0;
    for (int i = 0; i < chunk; ++i) {
        int idx = base + i;
        if (idx < Nn) {
            d_rowptr[idx] = run;
            run += d_counts[idx];
        }
    }
    if (t == 1023) d_rowptr[Nn] = run;
}

// ---------------- GEMM 128x128 body (split-fp16 m16n8k16, pre-split W, fp16 out) ----------------
template <bool BN, bool XH>
__device__ __forceinline__ void gemm128_body(
    const void* __restrict__ Xv,
    __half2* __restrict__ outh,
    const float* __restrict__ g, const float* __restrict__ be,
    int wlayer, int layer, int M, int bid)
{
    __shared__ uint32_t Xhi[128][18], Xlo[128][18];
    __shared__ uint32_t Whs[128][20], Wls[128][20];
    __shared__ float ssc[128], ssh[128];

    const float* __restrict__ Xf = (const float*)Xv;
    const int2* __restrict__ Xh = (const int2*)Xv;

    const int tid = threadIdx.x;
    const int lane = tid & 31;
    const int warp = tid >> 5;
    const int gid = lane >> 2;
    const int tig = lane & 3;
    const int wm = warp >> 1;
    const int wn = warp & 1;
    const int row0 = bid * 128;

    if (BN) {
        if (tid < 128) {
            const float invN = 1.f / (float)NN;
            float mean = d_sum[layer][tid] * invN;
            float var = d_sumsq[layer][tid] * invN - mean * mean;
            float sc = g[tid] * rsqrtf(var + BN_EPS);
            ssc[tid] = sc;
            ssh[tid] = fmaf(-mean, sc, be[tid]);
        }
        __syncthreads();
    }

    float c[2][8][4];
#pragma unroll
    for (int mt = 0; mt < 2; ++mt)
#pragma unroll
        for (int nt = 0; nt < 8; ++nt)
#pragma unroll
            for (int q = 0; q < 4; ++q) c[mt][nt][q] = 0.f;

    for (int kt = 0; kt < 4; ++kt) {
        const int k0 = kt * 32;
        {
            const uint32_t* __restrict__ Whg = d_Whi + (wlayer * 4 + kt) * 2048;
            const uint32_t* __restrict__ Wlg = d_Wlo + (wlayer * 4 + kt) * 2048;
#pragma unroll
            for (int l = 0; l < 2; ++l) {
                int idx = tid + 256 * l;
                int n = idx >> 2;
                int q = idx & 3;
                uint4 h = *reinterpret_cast<const uint4*>(&Whg[n * 16 + 4 * q]);
                uint4 lo = *reinterpret_cast<const uint4*>(&Wlg[n * 16 + 4 * q]);
                *reinterpret_cast<uint4*>(&Whs[n][4 * q]) = h;
                *reinterpret_cast<uint4*>(&Wls[n][4 * q]) = lo;
            }
        }
#pragma unroll
        for (int l = 0; l < 4; ++l) {
            int idx = tid + 256 * l;
            int r = idx >> 3;
            int c4 = idx & 7;
            int grow = row0 + r;
            float4 v = make_float4(0.f, 0.f, 0.f, 0.f);
            if (grow < M) {
                if (XH) {
                    int2 raw = __ldg(&Xh[grow * 32 + (k0 >> 2) + c4]);
                    float2 f0 = __half22float2(*reinterpret_cast<__half2*>(&raw.x));
                    float2 f1 = __half22float2(*reinterpret_cast<__half2*>(&raw.y));
                    v = make_float4(f0.x, f0.y, f1.x, f1.y);
                } else {
                    v = *reinterpret_cast<const float4*>(&Xf[grow * 128 + k0 + c4 * 4]);
                }
            }
            if (BN) {
                int k = k0 + c4 * 4;
                v.x = fmaxf(fmaf(v.x, ssc[k + 0], ssh[k + 0]), 0.f);
                v.y = fmaxf(fmaf(v.y, ssc[k + 1], ssh[k + 1]), 0.f);
                v.z = fmaxf(fmaf(v.z, ssc[k + 2], ssh[k + 2]), 0.f);
                v.w = fmaxf(fmaf(v.w, ssc[k + 3], ssh[k + 3]), 0.f);
            }
            __half hx, lx, hy, ly, hz, lz, hw, lw;
            h16_split(v.x, hx, lx);
            h16_split(v.y, hy, ly);
            h16_split(v.z, hz, lz);
            h16_split(v.w, hw, lw);
            Xhi[r][c4 * 2 + 0] = pack_h2(hx, hy);
            Xhi[r][c4 * 2 + 1] = pack_h2(hz, hw);
            Xlo[r][c4 * 2 + 0] = pack_h2(lx, ly);
            Xlo[r][c4 * 2 + 1] = pack_h2(lz, lw);
        }
        __syncthreads();

#pragma unroll
        for (int ks2 = 0; ks2 < 16; ks2 += 8) {
            uint32_t ahi[2][4], alo[2][4];
#pragma unroll
            for (int mt = 0; mt < 2; ++mt) {
                int rb = wm * 32 + mt * 16;
                ahi[mt][0] = Xhi[rb + gid][ks2 + tig];
                ahi[mt][1] = Xhi[rb + gid + 8][ks2 + tig];
                ahi[mt][2] = Xhi[rb + gid][ks2 + tig + 4];
                ahi[mt][3] = Xhi[rb + gid + 8][ks2 + tig + 4];
                alo[mt][0] = Xlo[rb + gid][ks2 + tig];
                alo[mt][1] = Xlo[rb + gid + 8][ks2 + tig];
                alo[mt][2] = Xlo[rb + gid][ks2 + tig + 4];
                alo[mt][3] = Xlo[rb + gid + 8][ks2 + tig + 4];
            }
#pragma unroll
            for (int nt = 0; nt < 8; ++nt) {
                int ncol = wn * 64 + nt * 8 + gid;
                uint32_t bh0 = Whs[ncol][ks2 + tig];
                uint32_t bh1 = Whs[ncol][ks2 + tig + 4];
                uint32_t bl0 = Wls[ncol][ks2 + tig];
                uint32_t bl1 = Wls[ncol][ks2 + tig + 4];
#pragma unroll
                for (int mt = 0; mt < 2; ++mt) {
                    mma_f16(c[mt][nt], ahi[mt], bh0, bh1);
                    mma_f16(c[mt][nt], alo[mt], bh0, bh1);
                    mma_f16(c[mt][nt], ahi[mt], bl0, bl1);
                }
            }
        }
        __syncthreads();
    }

#pragma unroll
    for (int mt = 0; mt < 2; ++mt) {
#pragma unroll
        for (int nt = 0; nt < 8; ++nt) {
            int col = wn * 64 + nt * 8 + 2 * tig;
            int r0 = row0 + wm * 32 + mt * 16 + gid;
            if (r0 < M)
                outh[r0 * 64 + (col >> 1)] =
                    __float22half2_rn(make_float2(c[mt][nt][0], c[mt][nt][1]));
            if (r0 + 8 < M)
                outh[(r0 + 8) * 64 + (col >> 1)] =
                    __float22half2_rn(make_float2(c[mt][nt][2], c[mt][nt][3]));
        }
    }
}

// phase A: CSR-hist blocks FIRST [0, hB), then gemm0 rows [0, gA)
__global__ __launch_bounds__(256) void fused0a_kernel(
    const float* __restrict__ x, __half2* __restrict__ outh,
    const int* __restrict__ er, int E, int M, int hB)
{
    if ((int)blockIdx.x < hB)
        hist_body(er, E, blockIdx.x);
    else
        gemm128_body<false, false>(x, outh, nullptr, nullptr, 0, 0, M, blockIdx.x - hB);
}

// phase B: scatter blocks FIRST [0, hB), then gemm0 rows [gA, g128)
__global__ __launch_bounds__(256) void fused0b_kernel(
    const float* __restrict__ x, __half2* __restrict__ outh,
    const int* __restrict__ er, const int* __restrict__ ec, const float* __restrict__ ew,
    int E, int M, int hB, int gA)
{
    if ((int)blockIdx.x < hB)
        scatter_body(er, ec, ew, E, blockIdx.x);
    else
        gemm128_body<false, false>(x, outh, nullptr, nullptr, 0, 0, M, blockIdx.x - hB + gA);
}

__global__ __launch_bounds__(256) void gemm128h_kernel(
    const int2* __restrict__ X, __half2* __restrict__ outh,
    const float* __restrict__ g, const float* __restrict__ be,
    int layer, int M)
{
    gemm128_body<true, true>(X, outh, g, be, 1, layer, M, blockIdx.x);
}

// ---------------- GEMM F=40 (fp16 in, fp32 compute, fp16 out, BN fused) ----------------
__global__ __launch_bounds__(256) void gemm40_kernel(
    const int2* __restrict__ Xh, const float* __restrict__ W,
    __half* __restrict__ outh,
    const float* __restrict__ g, const float* __restrict__ be,
    int layer, int M)
{
    constexpr int F = FOUT;
    __shared__ float Xs[64][64];
    __shared__ float Ws[64][F];
    __shared__ float ssc[128], ssh[128];

    const int tx = threadIdx.x;
    const int ty = threadIdx.y;
    const int tid = ty * 32 + tx;
    const int row0 = blockIdx.x * 64;

    if (tid < 128) {
        const float invN = 1.f / (float)NN;
        float mean = d_sum[layer][tid] * invN;
        float var = d_sumsq[layer][tid] * invN - mean * mean;
        float sc = g[tid] * rsqrtf(var + BN_EPS);
        ssc[tid] = sc;
        ssh[tid] = fmaf(-mean, sc, be[tid]);
    }
    __syncthreads();

    float acc[8][2];
#pragma unroll
    for (int i = 0; i < 8; ++i) { acc[i][0] = 0.f; acc[i][1] = 0.f; }

    for (int kt = 0; kt < 2; ++kt) {
        const int k0 = kt * 64;
        {
            const int nv4 = 64 * F / 4;
            for (int idx = tid; idx < nv4; idx += 256) {
                int r = idx / (F / 4);
                int c4 = idx % (F / 4);
                float4 v = *reinterpret_cast<const float4*>(&W[(k0 + r) * F + c4 * 4]);
                *reinterpret_cast<float4*>(&Ws[r][c4 * 4]) = v;
            }
        }
        {
#pragma unroll
            for (int l = 0; l < 4; ++l) {
                int idx = tid + 256 * l;
                int r = idx >> 4;
                int c4 = idx & 15;
                int grow = row0 + r;
                float4 v = make_float4(0.f, 0.f, 0.f, 0.f);
                if (grow < M) {
                    int2 raw = __ldg(&Xh[grow * 32 + (k0 >> 2) + c4]);
                    float2 f0 = __half22float2(*reinterpret_cast<__half2*>(&raw.x));
                    float2 f1 = __half22float2(*reinterpret_cast<__half2*>(&raw.y));
                    v = make_float4(f0.x, f0.y, f1.x, f1.y);
                }
                int k = k0 + c4 * 4;
                v.x = fmaxf(fmaf(v.x, ssc[k + 0], ssh[k + 0]), 0.f);
                v.y = fmaxf(fmaf(v.y, ssc[k + 1], ssh[k + 1]), 0.f);
                v.z = fmaxf(fmaf(v.z, ssc[k + 2], ssh[k + 2]), 0.f);
                v.w = fmaxf(fmaf(v.w, ssc[k + 3], ssh[k + 3]), 0.f);
                *reinterpret_cast<float4*>(&Xs[r][c4 * 4]) = v;
            }
        }
        __syncthreads();

#pragma unroll 4
        for (int kk = 0; kk < 64; ++kk) {
            float b0 = Ws[kk][tx];
            float b1 = (tx < 8) ? Ws[kk][32 + tx] : 0.f;
#pragma unroll
            for (int i = 0; i < 8; ++i) {
                float a = Xs[ty + 8 * i][kk];
                acc[i][0] = fmaf(a, b0, acc[i][0]);
                acc[i][1] = fmaf(a, b1, acc[i][1]);
            }
        }
        __syncthreads();
    }

#pragma unroll
    for (int i = 0; i < 8; ++i) {
        int grow = row0 + ty + 8 * i;
        if (grow < M) {
            outh[grow * F + tx] = __float2half_rn(acc[i][0]);
            if (tx < 8) outh[grow * F + 32 + tx] = __float2half_rn(acc[i][1]);
        }
    }
}

// ---------------- SpMM F=128 (fp16 gathers, fp16 out) + BN stats tree-reduce ----------------
__global__ __launch_bounds__(256) void spmm128_kernel(
    const int2* __restrict__ h,
    const float* __restrict__ bias,
    int2* __restrict__ outh, int layer, int M)
{
    __shared__ float sacc[8][128];
    const int warp = blockIdx.x * 8 + (threadIdx.x >> 5);
    const int wid = threadIdx.x >> 5;
    const int lane = threadIdx.x & 31;
    const int tid = threadIdx.x;

    float4 acc = make_float4(0.f, 0.f, 0.f, 0.f);
    if (warp < M) {
        const int s = d_rowptr[warp];
        const int e = d_rowptr[warp + 1];
        int base = s;
        for (; base + 32 <= e; base += 32) {
            int2 md = d_ecolw[base + lane];
            int colr = md.x;
            float wr = __int_as_float(md.y);
#pragma unroll
            for (int j = 0; j < 32; ++j) {
                int col = __shfl_sync(0xffffffffu, colr, j);
                float w = __shfl_sync(0xffffffffu, wr, j);
                int2 raw = __ldg(&h[col * 32 + lane]);
                float2 f0 = __half22float2(*reinterpret_cast<__half2*>(&raw.x));
                float2 f1 = __half22float2(*reinterpret_cast<__half2*>(&raw.y));
                acc.x = fmaf(w, f0.x, acc.x);
                acc.y = fmaf(w, f0.y, acc.y);
                acc.z = fmaf(w, f1.x, acc.z);
                acc.w = fmaf(w, f1.y, acc.w);
            }
        }
        if (base < e) {
            int n = e - base;
            int2 md = (lane < n) ? d_ecolw[base + lane] : make_int2(0, 0);
            int colr = md.x;
            float wr = __int_as_float(md.y);
            for (int j = 0; j < n; ++j) {
                int col = __shfl_sync(0xffffffffu, colr, j);
                float w = __shfl_sync(0xffffffffu, wr, j);
                int2 raw = __ldg(&h[col * 32 + lane]);
                float2 f0 = __half22float2(*reinterpret_cast<__half2*>(&raw.x));
                float2 f1 = __half22float2(*reinterpret_cast<__half2*>(&raw.y));
                acc.x = fmaf(w, f0.x, acc.x);
                acc.y = fmaf(w, f0.y, acc.y);
                acc.z = fmaf(w, f1.x, acc.z);
                acc.w = fmaf(w, f1.y, acc.w);
            }
        }
        const int f0i = lane * 4;
        float4 b = *reinterpret_cast<const float4*>(&bias[f0i]);
        acc.x += b.x; acc.y += b.y; acc.z += b.z; acc.w += b.w;
        __half2 h0 = __float22half2_rn(make_float2(acc.x, acc.y));
        __half2 h1 = __float22half2_rn(make_float2(acc.z, acc.w));
        int2 packed;
        packed.x = *reinterpret_cast<int*>(&h0);
        packed.y = *reinterpret_cast<int*>(&h1);
        outh[warp * 32 + lane] = packed;
    }
    *reinterpret_cast<float4*>(&sacc[wid][lane * 4]) = acc;
    __syncthreads();
    if (tid < 128) {
        float s = 0.f, s2 = 0.f;
#pragma unroll
        for (int w = 0; w < 8; ++w) {
            float v = sacc[w][tid];
            s += v;
            s2 = fmaf(v, v, s2);
        }
        atomicAdd(&d_sum[layer][tid], s);
        atomicAdd(&d_sumsq[layer][tid], s2);
    }
}

// ---------------- SpMM F=40 (fp16 gathers, fp32 accum & output) ----------------
__global__ __launch_bounds__(256) void spmm40_kernel(
    const __half2* __restrict__ h,
    const float* __restrict__ bias,
    float* __restrict__ out, int M)
{
    const int warp = blockIdx.x * 8 + (threadIdx.x >> 5);
    const int lane = threadIdx.x & 31;
    if (warp >= M) return;
    const int s = d_rowptr[warp];
    const int e = d_rowptr[warp + 1];

    float2 acc = make_float2(0.f, 0.f);
    int base = s;
    for (; base + 32 <= e; base += 32) {
        int2 md = d_ecolw[base + lane];
        int colr = md.x;
        float wr = __int_as_float(md.y);
#pragma unroll
        for (int j = 0; j < 32; ++j) {
            int col = __shfl_sync(0xffffffffu, colr, j);
            float w = __shfl_sync(0xffffffffu, wr, j);
            if (lane < 20) {
                float2 v = __half22float2(__ldg(&h[col * 20 + lane]));
                acc.x = fmaf(w, v.x, acc.x);
                acc.y = fmaf(w, v.y, acc.y);
            }
        }
    }
    if (base < e) {
        int n = e - base;
        int2 md = (lane < n) ? d_ecolw[base + lane] : make_int2(0, 0);
        int colr = md.x;
        float wr = __int_as_float(md.y);
        for (int j = 0; j < n; ++j) {
            int col = __shfl_sync(0xffffffffu, colr, j);
            float w = __shfl_sync(0xffffffffu, wr, j);
            if (lane < 20) {
                float2 v = __half22float2(__ldg(&h[col * 20 + lane]));
                acc.x = fmaf(w, v.x, acc.x);
                acc.y = fmaf(w, v.y, acc.y);
            }
        }
    }
    if (lane < 20) {
        acc.x += bias[2 * lane];
        acc.y += bias[2 * lane + 1];
        *reinterpret_cast<float2*>(&out[warp * FOUT + 2 * lane]) = acc;
    }
}

// ---------------- launch ----------------
extern "C" void kernel_launch(void* const* d_in, const int* in_sizes, int n_in,
                              void* d_out, int out_size)
{
    const float* x   = (const float*)d_in[0];
    const int*   er  = (const int*)d_in[1];
    const int*   ec  = (const int*)d_in[2];
    const float* ew  = (const float*)d_in[3];
    const float* W0  = (const float*)d_in[4];
    const float* b0  = (const float*)d_in[5];
    const float* g0  = (const float*)d_in[6];
    const float* be0 = (const float*)d_in[7];
    const float* W1  = (const float*)d_in[8];
    const float* b1  = (const float*)d_in[9];
    const float* g1  = (const float*)d_in[10];
    const float* be1 = (const float*)d_in[11];
    const float* W2  = (const float*)d_in[12];
    const float* b2  = (const float*)d_in[13];
    float* out = (float*)d_out;

    const int M = in_sizes[0] / FIN;
    const int E = in_sizes[1];

    int2*   t0h; cudaGetSymbolAddress((void**)&t0h, d_t0h);
    int2*   t1h; cudaGetSymbolAddress((void**)&t1h, d_t1h);
    __half* t2h; cudaGetSymbolAddress((void**)&t2h, d_t2h);

    const int g128 = (M + 127) / 128;
    const int gsp  = (M + 7) / 8;
    const int E16  = (E + 15) / 16;
    const int hB   = (E16 + 255) / 256;   // 16 edges/thread CSR blocks
    const int gA   = g128 / 2;
    const int gemmB = g128 - gA;

    // zero counts/sums + pre-split W0/W1
    zero_kernel<<<(NN + 255) / 256, 256>>>(W0, W1);
    // phase A: hist (first) ∥ gemm0 first half
    fused0a_kernel<<<hB + gA, 256>>>(x, (__half2*)t0h, er, E, M, hB);
    scan_kernel<<<1, 1024>>>(M);
    // phase B: scatter (first) ∥ gemm0 second half
    fused0b_kernel<<<hB + gemmB, 256>>>(x, (__half2*)t0h, er, ec, ew, E, M, hB, gA);

    // layer 0 aggregate
    spmm128_kernel<<<gsp, 256>>>(t0h, b0, t1h, 0, M);

    // layer 1 (BN finalize of layer-0 stats fused into gemm prologue)
    gemm128h_kernel<<<g128, 256>>>(t1h, (__half2*)t0h, g0, be0, 0, M);
    spmm128_kernel<<<gsp, 256>>>(t0h, b1, t1h, 1, M);

    // layer 2 (BN finalize of layer-1 stats fused into gemm40 prologue)
    gemm40_kernel<<<(M + 63) / 64, dim3(32, 8)>>>(t1h, W2, t2h, g1, be1, 1, M);
    spmm40_kernel<<<gsp, 256>>>((const __half2*)t2h, b2, out, M);
}